// round 1
// baseline (speedup 1.0000x reference)
#include <cuda_runtime.h>

#define S_DIM 4
#define N_DIM 4096
#define D_DIM 64
#define BATCH 2

// 4 MiB scratch for Q[s,j,d] = sum_e x0[s,j,e] * W[d,e]
__device__ float g_Q[S_DIM * N_DIM * D_DIM];

// ---------------------------------------------------------------------------
// Load a 64x64 fp32 tile (row-major, contiguous, row stride 64) from global
// into shared memory TRANSPOSED: logical element (row=x, col=k) lands at
//   smem[k*64 + ((x>>2) ^ ((k>>2)&15))*4 + (x&3)]
// The XOR swizzle keeps float4 granularity for the compute-side LDS.128 reads
// and limits the transpose-scatter STS conflicts to ~2-way.
// ---------------------------------------------------------------------------
__device__ __forceinline__ void load_tile_transposed(
    const float* __restrict__ gsrc, float* sdst, int t)
{
    const float4* g4 = reinterpret_cast<const float4*>(gsrc);
#pragma unroll
    for (int p = 0; p < 4; ++p) {
        int f4 = p * 256 + t;          // 0..1023 float4s of the 64x64 tile
        int x  = f4 >> 4;              // source row 0..63
        int k4 = (f4 & 15) << 2;       // source col base 0,4,...,60
        float4 v = g4[f4];
        float vv[4] = {v.x, v.y, v.z, v.w};
#pragma unroll
        for (int q = 0; q < 4; ++q) {
            int k  = k4 + q;
            int c4 = (x >> 2) ^ ((k >> 2) & 15);
            sdst[k * 64 + c4 * 4 + (x & 3)] = vv[q];
        }
    }
}

// ---------------------------------------------------------------------------
// 64x64x64 tile MMA on swizzled-transposed smem tiles.
// Thread (ty,tx) owns C rows ty*4..ty*4+3, cols tx*4..tx*4+3.
// Per k: 2x LDS.128 (conflict-free) + 16 FFMA.
// ---------------------------------------------------------------------------
__device__ __forceinline__ void mma_tile(
    const float* As, const float* Bs, int ty, int tx, float acc[4][4])
{
#pragma unroll
    for (int k = 0; k < 64; ++k) {
        int sw  = (k >> 2) & 15;
        float4 a = *reinterpret_cast<const float4*>(&As[k * 64 + ((ty ^ sw) << 2)]);
        float4 b = *reinterpret_cast<const float4*>(&Bs[k * 64 + ((tx ^ sw) << 2)]);
        float av[4] = {a.x, a.y, a.z, a.w};
        float bv[4] = {b.x, b.y, b.z, b.w};
#pragma unroll
        for (int ra = 0; ra < 4; ++ra)
#pragma unroll
            for (int rb = 0; rb < 4; ++rb)
                acc[ra][rb] += av[ra] * bv[rb];
    }
}

// ---------------------------------------------------------------------------
// Stage 1: Q[r,d] = sum_e X[r,e] * W[d,e], r = s*4096 + j flattened (16384 rows)
// One block per 64 rows; W tile (64x64) reloaded per block (L2-resident).
// ---------------------------------------------------------------------------
__global__ __launch_bounds__(256) void q_kernel(
    const float* __restrict__ x0, const float* __restrict__ W)
{
    __shared__ float Xs[64 * 64];
    __shared__ float Ws[64 * 64];
    int t  = threadIdx.x;
    int r0 = blockIdx.x * 64;

    load_tile_transposed(x0 + (size_t)r0 * 64, Xs, t);
    load_tile_transposed(W, Ws, t);
    __syncthreads();

    int tx = t & 15, ty = t >> 4;
    float acc[4][4] = {};
    mma_tile(Xs, Ws, ty, tx, acc);

#pragma unroll
    for (int ra = 0; ra < 4; ++ra) {
        int r = r0 + ty * 4 + ra;
        float4 v = make_float4(acc[ra][0], acc[ra][1], acc[ra][2], acc[ra][3]);
        *reinterpret_cast<float4*>(&g_Q[(size_t)r * 64 + tx * 4]) = v;
    }
}

// ---------------------------------------------------------------------------
// Stage 2: out[b,s,i,j] = sum_d x1[s,i,d] * Q[s,j,d] + bias, for b = 0,1
// Grid: (j-tiles=64, i-tiles=64, s=4); 64x64 C tile per block.
// ---------------------------------------------------------------------------
__global__ __launch_bounds__(256) void bilinear_kernel(
    const float* __restrict__ x1, const float* __restrict__ bias,
    float* __restrict__ out)
{
    __shared__ float As[64 * 64];
    __shared__ float Bs[64 * 64];
    int t  = threadIdx.x;
    int s  = blockIdx.z;
    int i0 = blockIdx.y * 64;
    int j0 = blockIdx.x * 64;

    const float* A  = x1  + ((size_t)s * N_DIM + i0) * D_DIM;
    const float* Bq = g_Q + ((size_t)s * N_DIM + j0) * D_DIM;

    load_tile_transposed(A, As, t);
    load_tile_transposed(Bq, Bs, t);
    __syncthreads();

    int tx = t & 15, ty = t >> 4;
    float acc[4][4] = {};
    mma_tile(As, Bs, ty, tx, acc);

    float bv = __ldg(bias);
    const size_t batch_stride = (size_t)S_DIM * N_DIM * N_DIM;

#pragma unroll
    for (int ra = 0; ra < 4; ++ra) {
        int i = i0 + ty * 4 + ra;
        size_t off = ((size_t)s * N_DIM + i) * N_DIM + j0 + tx * 4;
        float4 v = make_float4(acc[ra][0] + bv, acc[ra][1] + bv,
                               acc[ra][2] + bv, acc[ra][3] + bv);
        *reinterpret_cast<float4*>(&out[off])                = v;
        *reinterpret_cast<float4*>(&out[off + batch_stride]) = v;
    }
}

extern "C" void kernel_launch(void* const* d_in, const int* in_sizes, int n_in,
                              void* d_out, int out_size)
{
    const float* x0   = (const float*)d_in[0];  // tensor0 (S,N,D)
    const float* x1   = (const float*)d_in[1];  // tensor1 (S,N,D)
    const float* W    = (const float*)d_in[2];  // kernel  (D,D)
    const float* bias = (const float*)d_in[3];  // scalar
    float* out = (float*)d_out;                 // (2,S,N,N)

    q_kernel<<<(S_DIM * N_DIM) / 64, 256>>>(x0, W);

    dim3 grid(N_DIM / 64, N_DIM / 64, S_DIM);
    bilinear_kernel<<<grid, 256>>>(x1, bias, out);
}

// round 3
// speedup vs baseline: 1.1135x; 1.1135x over previous
#include <cuda_runtime.h>
#include <cstdint>

#define S_DIM 4
#define N_DIM 4096
#define D_DIM 64

// 4 MiB scratch for Q[s,j,d] = sum_e x0[s,j,e] * W[d,e]   (fp32)
__device__ float g_Q[S_DIM * N_DIM * D_DIM];

__device__ __forceinline__ float tf32_round(float x) {
    float y;
    asm("cvt.rna.tf32.f32 %0, %1;" : "=f"(y) : "f"(x));
    return y;
}

// mma.sync m16n8k8 tf32 (baseline PTX, works on compute_103)
__device__ __forceinline__ void mma_tf32(float d[4], const uint32_t a[4], const uint32_t b[2]) {
    asm volatile(
        "mma.sync.aligned.m16n8k8.row.col.f32.tf32.tf32.f32 "
        "{%0,%1,%2,%3}, {%4,%5,%6,%7}, {%8,%9}, {%0,%1,%2,%3};"
        : "+f"(d[0]), "+f"(d[1]), "+f"(d[2]), "+f"(d[3])
        : "r"(a[0]), "r"(a[1]), "r"(a[2]), "r"(a[3]), "r"(b[0]), "r"(b[1]));
}

// ---------------------------------------------------------------------------
// Stage 1: Q[r,d] = sum_e x0[r,e] * W[d,e]  (SIMT fp32, 64x64 tiles)
// ---------------------------------------------------------------------------
__device__ __forceinline__ void load_tile_transposed64(
    const float* __restrict__ gsrc, float* sdst, int t)
{
    const float4* g4 = reinterpret_cast<const float4*>(gsrc);
#pragma unroll
    for (int p = 0; p < 4; ++p) {
        int f4 = p * 256 + t;
        int x  = f4 >> 4;
        int k4 = (f4 & 15) << 2;
        float4 v = g4[f4];
        float vv[4] = {v.x, v.y, v.z, v.w};
#pragma unroll
        for (int q = 0; q < 4; ++q) {
            int k  = k4 + q;
            int c4 = (x >> 2) ^ ((k >> 2) & 15);
            sdst[k * 64 + c4 * 4 + (x & 3)] = vv[q];
        }
    }
}

__global__ __launch_bounds__(256) void q_kernel(
    const float* __restrict__ x0, const float* __restrict__ W)
{
    __shared__ float Xs[64 * 64];
    __shared__ float Ws[64 * 64];
    int t  = threadIdx.x;
    int r0 = blockIdx.x * 64;

    load_tile_transposed64(x0 + (size_t)r0 * 64, Xs, t);
    load_tile_transposed64(W, Ws, t);
    __syncthreads();

    int tx = t & 15, ty = t >> 4;
    float acc[4][4] = {};
#pragma unroll
    for (int k = 0; k < 64; ++k) {
        int sw = (k >> 2) & 15;
        float4 a = *reinterpret_cast<const float4*>(&Xs[k * 64 + ((ty ^ sw) << 2)]);
        float4 b = *reinterpret_cast<const float4*>(&Ws[k * 64 + ((tx ^ sw) << 2)]);
        float av[4] = {a.x, a.y, a.z, a.w};
        float bv[4] = {b.x, b.y, b.z, b.w};
#pragma unroll
        for (int ra = 0; ra < 4; ++ra)
#pragma unroll
            for (int rb = 0; rb < 4; ++rb)
                acc[ra][rb] += av[ra] * bv[rb];
    }

#pragma unroll
    for (int ra = 0; ra < 4; ++ra) {
        int r = r0 + ty * 4 + ra;
        float4 v = make_float4(acc[ra][0], acc[ra][1], acc[ra][2], acc[ra][3]);
        *reinterpret_cast<float4*>(&g_Q[(size_t)r * 64 + tx * 4]) = v;
    }
}

// ---------------------------------------------------------------------------
// Stage 2: 3xTF32 mma.sync GEMM.
// CTA = 128x128 C tile, 256 threads = 8 warps in 2(m) x 4(n), warp = 64x32.
// Smem: 4 padded tiles [128][68] fp32 (A-hi, A-lo, B-hi, B-lo), 136 KB.
// ---------------------------------------------------------------------------
#define PAD 68
#define TILE_FLOATS (128 * PAD)
#define SMEM_DYN (4 * TILE_FLOATS * 4)

// Load a 128x64 fp32 tile and split into tf32 hi/lo padded smem tiles.
__device__ __forceinline__ void fill_split(
    const float* __restrict__ gsrc, float* hi, float* lo, int t)
{
    const float4* g4 = reinterpret_cast<const float4*>(gsrc);
#pragma unroll
    for (int it = 0; it < 8; ++it) {
        int f4 = it * 256 + t;         // 0..2047
        int r  = f4 >> 4;
        int c4 = f4 & 15;
        float4 v = g4[f4];
        float4 h, l;
        h.x = tf32_round(v.x); l.x = tf32_round(v.x - h.x);
        h.y = tf32_round(v.y); l.y = tf32_round(v.y - h.y);
        h.z = tf32_round(v.z); l.z = tf32_round(v.z - h.z);
        h.w = tf32_round(v.w); l.w = tf32_round(v.w - h.w);
        *reinterpret_cast<float4*>(&hi[r * PAD + c4 * 4]) = h;
        *reinterpret_cast<float4*>(&lo[r * PAD + c4 * 4]) = l;
    }
}

__global__ __launch_bounds__(256, 1) void bilinear_mma_kernel(
    const float* __restrict__ x1, const float* __restrict__ bias,
    float* __restrict__ out)
{
    extern __shared__ float sm[];
    float* Ah = sm;
    float* Al = sm + TILE_FLOATS;
    float* Bh = sm + 2 * TILE_FLOATS;
    float* Bl = sm + 3 * TILE_FLOATS;

    int t    = threadIdx.x;
    int warp = t >> 5;
    int lane = t & 31;
    int wm   = warp >> 2;      // 0..1  (m direction, 64 rows each)
    int wn   = warp & 3;       // 0..3  (n direction, 32 cols each)
    int g    = lane >> 2;      // group id 0..7
    int tg   = lane & 3;       // thread-in-group 0..3

    int s  = blockIdx.z;
    int i0 = blockIdx.y * 128;
    int j0 = blockIdx.x * 128;

    // Fill smem tiles (x1 rows i0.., Q rows j0..), splitting fp32 -> tf32 hi/lo
    fill_split(x1 + ((size_t)s * N_DIM + i0) * D_DIM, Ah, Al, t);
    fill_split(g_Q + ((size_t)s * N_DIM + j0) * D_DIM, Bh, Bl, t);
    __syncthreads();

    float acc[4][4][4];        // [mt][nt][reg]
#pragma unroll
    for (int a = 0; a < 4; ++a)
#pragma unroll
        for (int b = 0; b < 4; ++b)
#pragma unroll
            for (int c = 0; c < 4; ++c) acc[a][b][c] = 0.0f;

    // Per-warp base pointers (lane part makes banks == lane: conflict-free)
    const float* pAh = Ah + (wm * 64 + g) * PAD + tg;
    const float* pAl = Al + (wm * 64 + g) * PAD + tg;
    const float* pBh = Bh + (wn * 32 + g) * PAD + tg;
    const float* pBl = Bl + (wn * 32 + g) * PAD + tg;

#pragma unroll
    for (int kt = 0; kt < 8; ++kt) {
        int k0 = kt * 8;
        uint32_t ah[4][4], al[4][4];   // [mt][reg]
        uint32_t bh[4][2], bl[4][2];   // [nt][reg]
#pragma unroll
        for (int mt = 0; mt < 4; ++mt) {
#pragma unroll
            for (int q = 0; q < 4; ++q) {
                int off = (mt * 16 + 8 * (q & 1)) * PAD + k0 + 4 * (q >> 1);
                ah[mt][q] = __float_as_uint(pAh[off]);
                al[mt][q] = __float_as_uint(pAl[off]);
            }
        }
#pragma unroll
        for (int nt = 0; nt < 4; ++nt) {
#pragma unroll
            for (int q = 0; q < 2; ++q) {
                int off = (nt * 8) * PAD + k0 + 4 * q;
                bh[nt][q] = __float_as_uint(pBh[off]);
                bl[nt][q] = __float_as_uint(pBl[off]);
            }
        }
#pragma unroll
        for (int mt = 0; mt < 4; ++mt)
#pragma unroll
            for (int nt = 0; nt < 4; ++nt) {
                mma_tf32(acc[mt][nt], ah[mt], bh[nt]);   // hi*hi
                mma_tf32(acc[mt][nt], al[mt], bh[nt]);   // lo*hi
                mma_tf32(acc[mt][nt], ah[mt], bl[nt]);   // hi*lo
            }
    }

    float bv = __ldg(bias);
    const size_t batch_stride = (size_t)S_DIM * N_DIM * N_DIM;

    // Epilogue: c0,c1 -> (row g, cols 2tg,2tg+1); c2,c3 -> row g+8
#pragma unroll
    for (int mt = 0; mt < 4; ++mt) {
#pragma unroll
        for (int h = 0; h < 2; ++h) {
            int i = i0 + wm * 64 + mt * 16 + g + 8 * h;
            size_t rowoff = ((size_t)s * N_DIM + i) * N_DIM;
#pragma unroll
            for (int nt = 0; nt < 4; ++nt) {
                int j = j0 + wn * 32 + nt * 8 + 2 * tg;
                float2 v;
                v.x = acc[mt][nt][2 * h + 0] + bv;
                v.y = acc[mt][nt][2 * h + 1] + bv;
                *reinterpret_cast<float2*>(&out[rowoff + j])                = v;
                *reinterpret_cast<float2*>(&out[rowoff + j + batch_stride]) = v;
            }
        }
    }
}

extern "C" void kernel_launch(void* const* d_in, const int* in_sizes, int n_in,
                              void* d_out, int out_size)
{
    const float* x0   = (const float*)d_in[0];  // tensor0 (S,N,D)
    const float* x1   = (const float*)d_in[1];  // tensor1 (S,N,D)
    const float* W    = (const float*)d_in[2];  // kernel  (D,D)
    const float* bias = (const float*)d_in[3];  // scalar
    float* out = (float*)d_out;                 // (2,S,N,N)

    cudaFuncSetAttribute(bilinear_mma_kernel,
                         cudaFuncAttributeMaxDynamicSharedMemorySize, SMEM_DYN);

    q_kernel<<<(S_DIM * N_DIM) / 64, 256>>>(x0, W);

    dim3 grid(N_DIM / 128, N_DIM / 128, S_DIM);
    bilinear_mma_kernel<<<grid, 256, SMEM_DYN>>>(x1, bias, out);
}

// round 4
// speedup vs baseline: 1.4938x; 1.3416x over previous
#include <cuda_runtime.h>
#include <cstdint>

#define S_DIM 4
#define N_DIM 4096
#define D_DIM 64

// 4 MiB scratch for Q[s,j,d] = sum_e x0[s,j,e] * W[d,e]   (fp32)
__device__ float g_Q[S_DIM * N_DIM * D_DIM];

__device__ __forceinline__ float tf32_round(float x) {
    float y;
    asm("cvt.rna.tf32.f32 %0, %1;" : "=f"(y) : "f"(x));
    return y;
}
__device__ __forceinline__ uint32_t smem_u32(const void* p) {
    uint32_t a;
    asm("{ .reg .u64 t; cvta.to.shared.u64 t, %1; cvt.u32.u64 %0, t; }"
        : "=r"(a) : "l"(p));
    return a;
}

// mma.sync m16n8k8 tf32 (baseline PTX, valid on compute_103)
__device__ __forceinline__ void mma_tf32(float d[4], const uint32_t a[4], const uint32_t b[2]) {
    asm volatile(
        "mma.sync.aligned.m16n8k8.row.col.f32.tf32.tf32.f32 "
        "{%0,%1,%2,%3}, {%4,%5,%6,%7}, {%8,%9}, {%0,%1,%2,%3};"
        : "+f"(d[0]), "+f"(d[1]), "+f"(d[2]), "+f"(d[3])
        : "r"(a[0]), "r"(a[1]), "r"(a[2]), "r"(a[3]), "r"(b[0]), "r"(b[1]));
}

// ---------------------------------------------------------------------------
// Stage 1: Q[r,d] = sum_e x0[r,e] * W[d,e]  (SIMT fp32, 64x64 tiles)
// ---------------------------------------------------------------------------
__device__ __forceinline__ void load_tile_transposed64(
    const float* __restrict__ gsrc, float* sdst, int t)
{
    const float4* g4 = reinterpret_cast<const float4*>(gsrc);
#pragma unroll
    for (int p = 0; p < 4; ++p) {
        int f4 = p * 256 + t;
        int x  = f4 >> 4;
        int k4 = (f4 & 15) << 2;
        float4 v = g4[f4];
        float vv[4] = {v.x, v.y, v.z, v.w};
#pragma unroll
        for (int q = 0; q < 4; ++q) {
            int k  = k4 + q;
            int c4 = (x >> 2) ^ ((k >> 2) & 15);
            sdst[k * 64 + c4 * 4 + (x & 3)] = vv[q];
        }
    }
}

__global__ __launch_bounds__(256) void q_kernel(
    const float* __restrict__ x0, const float* __restrict__ W)
{
    __shared__ float Xs[64 * 64];
    __shared__ float Ws[64 * 64];
    int t  = threadIdx.x;
    int r0 = blockIdx.x * 64;

    load_tile_transposed64(x0 + (size_t)r0 * 64, Xs, t);
    load_tile_transposed64(W, Ws, t);
    __syncthreads();

    int tx = t & 15, ty = t >> 4;
    float acc[4][4] = {};
#pragma unroll
    for (int k = 0; k < 64; ++k) {
        int sw = (k >> 2) & 15;
        float4 a = *reinterpret_cast<const float4*>(&Xs[k * 64 + ((ty ^ sw) << 2)]);
        float4 b = *reinterpret_cast<const float4*>(&Ws[k * 64 + ((tx ^ sw) << 2)]);
        float av[4] = {a.x, a.y, a.z, a.w};
        float bv[4] = {b.x, b.y, b.z, b.w};
#pragma unroll
        for (int ra = 0; ra < 4; ++ra)
#pragma unroll
            for (int rb = 0; rb < 4; ++rb)
                acc[ra][rb] += av[ra] * bv[rb];
    }

#pragma unroll
    for (int ra = 0; ra < 4; ++ra) {
        int r = r0 + ty * 4 + ra;
        float4 v = make_float4(acc[ra][0], acc[ra][1], acc[ra][2], acc[ra][3]);
        *reinterpret_cast<float4*>(&g_Q[(size_t)r * 64 + tx * 4]) = v;
    }
}

// ---------------------------------------------------------------------------
// Stage 2: 3xTF32 mma.sync GEMM, on-the-fly hi/lo split.
// CTA = 128x128 C tile, 256 threads = 8 warps (2m x 4n), warp = 64x32.
// Smem: 2 raw fp32 tiles [128][68] (A = x1 rows, B = Q rows), 68 KB.
// 2 CTAs/SM (launch_bounds regs<=128) for latency overlap.
// ---------------------------------------------------------------------------
#define PAD 68
#define TILE_FLOATS (128 * PAD)
#define SMEM_DYN (2 * TILE_FLOATS * 4)

__device__ __forceinline__ void fill_tile_async(
    const float* __restrict__ gsrc, float* sdst, int t)
{
#pragma unroll
    for (int it = 0; it < 8; ++it) {
        int f4 = it * 256 + t;         // 0..2047 float4s of 128x64 tile
        int r  = f4 >> 4;
        int c4 = f4 & 15;
        uint32_t sa = smem_u32(&sdst[r * PAD + c4 * 4]);
        asm volatile("cp.async.cg.shared.global [%0], [%1], 16;"
                     :: "r"(sa), "l"(gsrc + f4 * 4) : "memory");
    }
}

__global__ __launch_bounds__(256, 2) void bilinear_mma_kernel(
    const float* __restrict__ x1, const float* __restrict__ bias,
    float* __restrict__ out)
{
    extern __shared__ float sm[];
    float* As = sm;
    float* Bs = sm + TILE_FLOATS;

    int t    = threadIdx.x;
    int warp = t >> 5;
    int lane = t & 31;
    int wm   = warp >> 2;      // 0..1  (m direction, 64 rows)
    int wn   = warp & 3;       // 0..3  (n direction, 32 cols)
    int g    = lane >> 2;      // 0..7
    int tg   = lane & 3;       // 0..3

    int s  = blockIdx.z;
    int i0 = blockIdx.y * 128;
    int j0 = blockIdx.x * 128;

    fill_tile_async(x1 + ((size_t)s * N_DIM + i0) * D_DIM, As, t);
    fill_tile_async(g_Q + ((size_t)s * N_DIM + j0) * D_DIM, Bs, t);
    asm volatile("cp.async.commit_group;" ::: "memory");
    asm volatile("cp.async.wait_group 0;" ::: "memory");
    __syncthreads();

    float acc[4][4][4];
#pragma unroll
    for (int a = 0; a < 4; ++a)
#pragma unroll
        for (int b = 0; b < 4; ++b)
#pragma unroll
            for (int c = 0; c < 4; ++c) acc[a][b][c] = 0.0f;

    // lane-mapped base pointers: float index mod 32 = 4g+tg -> conflict-free
    const float* pA = As + (wm * 64 + g) * PAD + tg;
    const float* pB = Bs + (wn * 32 + g) * PAD + tg;

#pragma unroll
    for (int kt = 0; kt < 8; ++kt) {
        int k0 = kt * 8;

        // B fragments: split once, reuse across all mt
        uint32_t bh[4][2], bl[4][2];
#pragma unroll
        for (int nt = 0; nt < 4; ++nt)
#pragma unroll
            for (int q = 0; q < 2; ++q) {
                float v = pB[(nt * 8) * PAD + k0 + 4 * q];
                float h = tf32_round(v);
                bh[nt][q] = __float_as_uint(h);
                bl[nt][q] = __float_as_uint(tf32_round(v - h));
            }

#pragma unroll
        for (int mt = 0; mt < 4; ++mt) {
            uint32_t ah[4], al[4];
#pragma unroll
            for (int q = 0; q < 4; ++q) {
                float v = pA[(mt * 16 + 8 * (q & 1)) * PAD + k0 + 4 * (q >> 1)];
                float h = tf32_round(v);
                ah[q] = __float_as_uint(h);
                al[q] = __float_as_uint(tf32_round(v - h));
            }
#pragma unroll
            for (int nt = 0; nt < 4; ++nt) {
                mma_tf32(acc[mt][nt], ah, bh[nt]);   // hi*hi
                mma_tf32(acc[mt][nt], al, bh[nt]);   // lo*hi
                mma_tf32(acc[mt][nt], ah, bl[nt]);   // hi*lo
            }
        }
    }

    float bv = __ldg(bias);
    const size_t batch_stride = (size_t)S_DIM * N_DIM * N_DIM;

    // Epilogue: c0,c1 -> (row g, cols 2tg..); c2,c3 -> row g+8. Streaming stores.
#pragma unroll
    for (int mt = 0; mt < 4; ++mt) {
#pragma unroll
        for (int h = 0; h < 2; ++h) {
            int i = i0 + wm * 64 + mt * 16 + g + 8 * h;
            size_t rowoff = ((size_t)s * N_DIM + i) * N_DIM;
#pragma unroll
            for (int nt = 0; nt < 4; ++nt) {
                int j = j0 + wn * 32 + nt * 8 + 2 * tg;
                float2 v;
                v.x = acc[mt][nt][2 * h + 0] + bv;
                v.y = acc[mt][nt][2 * h + 1] + bv;
                __stcs(reinterpret_cast<float2*>(&out[rowoff + j]), v);
                __stcs(reinterpret_cast<float2*>(&out[rowoff + j + batch_stride]), v);
            }
        }
    }
}

extern "C" void kernel_launch(void* const* d_in, const int* in_sizes, int n_in,
                              void* d_out, int out_size)
{
    const float* x0   = (const float*)d_in[0];  // tensor0 (S,N,D)
    const float* x1   = (const float*)d_in[1];  // tensor1 (S,N,D)
    const float* W    = (const float*)d_in[2];  // kernel  (D,D)
    const float* bias = (const float*)d_in[3];  // scalar
    float* out = (float*)d_out;                 // (2,S,N,N)

    cudaFuncSetAttribute(bilinear_mma_kernel,
                         cudaFuncAttributeMaxDynamicSharedMemorySize, SMEM_DYN);

    q_kernel<<<(S_DIM * N_DIM) / 64, 256>>>(x0, W);

    dim3 grid(N_DIM / 128, N_DIM / 128, S_DIM);
    bilinear_mma_kernel<<<grid, 256, SMEM_DYN>>>(x1, bias, out);
}

// round 5
// speedup vs baseline: 1.5953x; 1.0680x over previous
#include <cuda_runtime.h>
#include <cstdint>

#define S_DIM 4
#define N_DIM 4096
#define D_DIM 64

// Packed split-bf16 scratch: word = (hi_bf16 in low16, lo_bf16 in high16)
__device__ uint32_t g_Xp[S_DIM * N_DIM * D_DIM];   // x1 split-packed
__device__ uint32_t g_Qp[S_DIM * N_DIM * D_DIM];   // Q  split-packed

__device__ __forceinline__ uint32_t smem_u32(const void* p) {
    uint32_t a;
    asm("{ .reg .u64 t; cvta.to.shared.u64 t, %1; cvt.u32.u64 %0, t; }"
        : "=r"(a) : "l"(p));
    return a;
}

// Pack fp32 -> (hi = truncate-to-bf16, lo = rne-bf16 of remainder)
__device__ __forceinline__ uint32_t split_pack(float v) {
    float hf = __uint_as_float(__float_as_uint(v) & 0xFFFF0000u);
    float l  = v - hf;
    uint32_t pk;
    // d = { high: bf16(l), low: bf16(hf) };  bf16(hf) exact (hf already bf16)
    asm("cvt.rn.bf16x2.f32 %0, %1, %2;" : "=r"(pk) : "f"(l), "f"(hf));
    return pk;
}

// bf16 mma m16n8k16 (baseline PTX, sm_80+, valid on compute_103)
__device__ __forceinline__ void mma_bf16(float d[4], const uint32_t a[4], const uint32_t b[2]) {
    asm volatile(
        "mma.sync.aligned.m16n8k16.row.col.f32.bf16.bf16.f32 "
        "{%0,%1,%2,%3}, {%4,%5,%6,%7}, {%8,%9}, {%0,%1,%2,%3};"
        : "+f"(d[0]), "+f"(d[1]), "+f"(d[2]), "+f"(d[3])
        : "r"(a[0]), "r"(a[1]), "r"(a[2]), "r"(a[3]), "r"(b[0]), "r"(b[1]));
}

__device__ __forceinline__ uint32_t prmt(uint32_t a, uint32_t b, uint32_t sel) {
    uint32_t d;
    asm("prmt.b32 %0, %1, %2, %3;" : "=r"(d) : "r"(a), "r"(b), "r"(sel));
    return d;
}

// ---------------------------------------------------------------------------
// Prep A: split-pack x1
// ---------------------------------------------------------------------------
__global__ __launch_bounds__(256) void split_x1_kernel(const float* __restrict__ x1) {
    int i = blockIdx.x * 256 + threadIdx.x;       // float4 index
    float4 v = reinterpret_cast<const float4*>(x1)[i];
    uint4 p;
    p.x = split_pack(v.x); p.y = split_pack(v.y);
    p.z = split_pack(v.z); p.w = split_pack(v.w);
    reinterpret_cast<uint4*>(g_Xp)[i] = p;
}

// ---------------------------------------------------------------------------
// Prep B: Q[r,d] = sum_e x0[r,e] * W[d,e]  (SIMT fp32), write split-packed
// ---------------------------------------------------------------------------
__device__ __forceinline__ void load_tile_transposed64(
    const float* __restrict__ gsrc, float* sdst, int t)
{
    const float4* g4 = reinterpret_cast<const float4*>(gsrc);
#pragma unroll
    for (int p = 0; p < 4; ++p) {
        int f4 = p * 256 + t;
        int x  = f4 >> 4;
        int k4 = (f4 & 15) << 2;
        float4 v = g4[f4];
        float vv[4] = {v.x, v.y, v.z, v.w};
#pragma unroll
        for (int q = 0; q < 4; ++q) {
            int k  = k4 + q;
            int c4 = (x >> 2) ^ ((k >> 2) & 15);
            sdst[k * 64 + c4 * 4 + (x & 3)] = vv[q];
        }
    }
}

__global__ __launch_bounds__(256) void q_kernel(
    const float* __restrict__ x0, const float* __restrict__ W)
{
    __shared__ float Xs[64 * 64];
    __shared__ float Ws[64 * 64];
    int t  = threadIdx.x;
    int r0 = blockIdx.x * 64;

    load_tile_transposed64(x0 + (size_t)r0 * 64, Xs, t);
    load_tile_transposed64(W, Ws, t);
    __syncthreads();

    int tx = t & 15, ty = t >> 4;
    float acc[4][4] = {};
#pragma unroll
    for (int k = 0; k < 64; ++k) {
        int sw = (k >> 2) & 15;
        float4 a = *reinterpret_cast<const float4*>(&Xs[k * 64 + ((ty ^ sw) << 2)]);
        float4 b = *reinterpret_cast<const float4*>(&Ws[k * 64 + ((tx ^ sw) << 2)]);
        float av[4] = {a.x, a.y, a.z, a.w};
        float bv[4] = {b.x, b.y, b.z, b.w};
#pragma unroll
        for (int ra = 0; ra < 4; ++ra)
#pragma unroll
            for (int rb = 0; rb < 4; ++rb)
                acc[ra][rb] += av[ra] * bv[rb];
    }

#pragma unroll
    for (int ra = 0; ra < 4; ++ra) {
        int r = r0 + ty * 4 + ra;
        uint4 p;
        p.x = split_pack(acc[ra][0]); p.y = split_pack(acc[ra][1]);
        p.z = split_pack(acc[ra][2]); p.w = split_pack(acc[ra][3]);
        *reinterpret_cast<uint4*>(&g_Qp[(size_t)r * 64 + tx * 4]) = p;
    }
}

// ---------------------------------------------------------------------------
// Stage 2: 4-pass split-bf16 mma.sync GEMM.
// CTA = 128x128 C tile, 256 threads = 8 warps (2m x 4n), warp = 64x32.
// Smem: 2 packed tiles [128][68] u32, 68 KB -> 2 CTAs/SM.
// ---------------------------------------------------------------------------
#define PAD 68
#define TILE_WORDS (128 * PAD)
#define SMEM_DYN (2 * TILE_WORDS * 4)

__device__ __forceinline__ void fill_tile_async(
    const uint32_t* __restrict__ gsrc, uint32_t* sdst, int t)
{
#pragma unroll
    for (int it = 0; it < 8; ++it) {
        int f4 = it * 256 + t;         // 0..2047 16B chunks of 128x64 tile
        int r  = f4 >> 4;
        int c4 = f4 & 15;
        uint32_t sa = smem_u32(&sdst[r * PAD + c4 * 4]);
        asm volatile("cp.async.cg.shared.global [%0], [%1], 16;"
                     :: "r"(sa), "l"(gsrc + f4 * 4) : "memory");
    }
}

__global__ __launch_bounds__(256, 2) void bilinear_mma_kernel(
    const float* __restrict__ bias, float* __restrict__ out)
{
    extern __shared__ uint32_t sm[];
    uint32_t* As = sm;
    uint32_t* Bs = sm + TILE_WORDS;

    int t    = threadIdx.x;
    int warp = t >> 5;
    int lane = t & 31;
    int wm   = warp >> 2;      // 0..1  (m, 64 rows)
    int wn   = warp & 3;       // 0..3  (n, 32 cols)
    int g    = lane >> 2;      // 0..7
    int tg   = lane & 3;       // 0..3

    int s  = blockIdx.z;
    int i0 = blockIdx.y * 128;
    int j0 = blockIdx.x * 128;

    fill_tile_async(g_Xp + ((size_t)s * N_DIM + i0) * D_DIM, As, t);
    fill_tile_async(g_Qp + ((size_t)s * N_DIM + j0) * D_DIM, Bs, t);
    asm volatile("cp.async.commit_group;" ::: "memory");
    asm volatile("cp.async.wait_group 0;" ::: "memory");
    __syncthreads();

    float acc[4][4][4];
#pragma unroll
    for (int a = 0; a < 4; ++a)
#pragma unroll
        for (int b = 0; b < 4; ++b)
#pragma unroll
            for (int c = 0; c < 4; ++c) acc[a][b][c] = 0.0f;

    const uint32_t* pA = As + (wm * 64 + g) * PAD + 2 * tg;
    const uint32_t* pB = Bs + (wn * 32 + g) * PAD + 2 * tg;

#pragma unroll
    for (int kt = 0; kt < 4; ++kt) {       // K = 4 x 16
        int k0 = kt * 16;

        // B fragments: split into hi/lo pairs once, reuse across mt
        uint32_t bh[4][2], bl[4][2];
#pragma unroll
        for (int nt = 0; nt < 4; ++nt) {
#pragma unroll
            for (int q = 0; q < 2; ++q) {   // k-pair at k0+2tg (+8)
                uint2 w = *reinterpret_cast<const uint2*>(&pB[(nt * 8) * PAD + k0 + 8 * q]);
                bh[nt][q] = prmt(w.x, w.y, 0x5410);  // (hi0, hi1)
                bl[nt][q] = prmt(w.x, w.y, 0x7632);  // (lo0, lo1)
            }
        }

#pragma unroll
        for (int mt = 0; mt < 4; ++mt) {
            uint32_t ah[4], al[4];
#pragma unroll
            for (int q = 0; q < 4; ++q) {   // rows g/g+8, k-pair k0 (+8)
                int off = (mt * 16 + 8 * (q & 1)) * PAD + k0 + 8 * (q >> 1);
                uint2 w = *reinterpret_cast<const uint2*>(&pA[off]);
                ah[q] = prmt(w.x, w.y, 0x5410);
                al[q] = prmt(w.x, w.y, 0x7632);
            }
#pragma unroll
            for (int nt = 0; nt < 4; ++nt) {
                mma_bf16(acc[mt][nt], ah, bh[nt]);   // hi*hi
                mma_bf16(acc[mt][nt], al, bh[nt]);   // lo*hi
                mma_bf16(acc[mt][nt], ah, bl[nt]);   // hi*lo
                mma_bf16(acc[mt][nt], al, bl[nt]);   // lo*lo
            }
        }
    }

    float bv = __ldg(bias);
    const size_t batch_stride = (size_t)S_DIM * N_DIM * N_DIM;

    // Epilogue: c0,c1 -> (row g, cols 2tg,2tg+1); c2,c3 -> row g+8
#pragma unroll
    for (int mt = 0; mt < 4; ++mt) {
#pragma unroll
        for (int h = 0; h < 2; ++h) {
            int i = i0 + wm * 64 + mt * 16 + g + 8 * h;
            size_t rowoff = ((size_t)s * N_DIM + i) * N_DIM;
#pragma unroll
            for (int nt = 0; nt < 4; ++nt) {
                int j = j0 + wn * 32 + nt * 8 + 2 * tg;
                float2 v;
                v.x = acc[mt][nt][2 * h + 0] + bv;
                v.y = acc[mt][nt][2 * h + 1] + bv;
                __stcs(reinterpret_cast<float2*>(&out[rowoff + j]), v);
                __stcs(reinterpret_cast<float2*>(&out[rowoff + j + batch_stride]), v);
            }
        }
    }
}

extern "C" void kernel_launch(void* const* d_in, const int* in_sizes, int n_in,
                              void* d_out, int out_size)
{
    const float* x0   = (const float*)d_in[0];  // tensor0 (S,N,D)
    const float* x1   = (const float*)d_in[1];  // tensor1 (S,N,D)
    const float* W    = (const float*)d_in[2];  // kernel  (D,D)
    const float* bias = (const float*)d_in[3];  // scalar
    float* out = (float*)d_out;                 // (2,S,N,N)

    cudaFuncSetAttribute(bilinear_mma_kernel,
                         cudaFuncAttributeMaxDynamicSharedMemorySize, SMEM_DYN);

    split_x1_kernel<<<(S_DIM * N_DIM * D_DIM) / (256 * 4), 256>>>(x1);
    q_kernel<<<(S_DIM * N_DIM) / 64, 256>>>(x0, W);

    dim3 grid(N_DIM / 128, N_DIM / 128, S_DIM);
    bilinear_mma_kernel<<<grid, 256, SMEM_DYN>>>(bias, out);
}